// round 17
// baseline (speedup 1.0000x reference)
#include <cuda_runtime.h>
#include <cuda_fp16.h>
#include <math.h>
#include <stdint.h>

constexpr int Bb = 32;
constexpr int Hh = 56;
constexpr int Ww = 56;
constexpr int Cc = 128;
constexpr int Nn = Hh * Ww;              // 3136
constexpr int Mm = Bb * Nn;              // 100352
constexpr size_t MC = (size_t)Mm * Cc;

__device__ float g_t0[MC];
__device__ float g_t1[MC];
__device__ float g_x1a[MC];
__device__ float g_x2a[MC];
__device__ float g_q[MC];
__device__ float g_k[MC];
__device__ float g_v[MC];
__device__ float g_att[MC];
__device__ float g_stats[2 * Mm];
__device__ float g_part[2048 * 256];
__device__ float g_s1[Cc];
__device__ float g_h1[Cc];
__device__ float g_s2[Cc];
__device__ float g_h2[Cc];

__device__ __forceinline__ void mma_tf32(float* c, const float4& a, const float2& b) {
    asm volatile(
        "mma.sync.aligned.m16n8k8.row.col.f32.tf32.tf32.f32 "
        "{%0,%1,%2,%3}, {%4,%5,%6,%7}, {%8,%9}, {%0,%1,%2,%3};"
        : "+f"(c[0]), "+f"(c[1]), "+f"(c[2]), "+f"(c[3])
        : "r"(__float_as_uint(a.x)), "r"(__float_as_uint(a.y)),
          "r"(__float_as_uint(a.z)), "r"(__float_as_uint(a.w)),
          "r"(__float_as_uint(b.x)), "r"(__float_as_uint(b.y)));
}

__device__ __forceinline__ void mma_f16(float* c, uint32_t a0, uint32_t a1,
                                        uint32_t a2, uint32_t a3,
                                        uint32_t b0, uint32_t b1) {
    asm volatile(
        "mma.sync.aligned.m16n8k16.row.col.f32.f16.f16.f32 "
        "{%0,%1,%2,%3}, {%4,%5,%6,%7}, {%8,%9}, {%0,%1,%2,%3};"
        : "+f"(c[0]), "+f"(c[1]), "+f"(c[2]), "+f"(c[3])
        : "r"(a0), "r"(a1), "r"(a2), "r"(a3), "r"(b0), "r"(b1));
}

__device__ __forceinline__ uint32_t pack2(float x, float y) {
    __half2 h = __floats2half2_rn(x, y);
    return *reinterpret_cast<uint32_t*>(&h);
}

__device__ __forceinline__ float4 half4_to_f4(uint2 hv) {
    float2 f0 = __half22float2(*reinterpret_cast<__half2*>(&hv.x));
    float2 f1 = __half22float2(*reinterpret_cast<__half2*>(&hv.y));
    return make_float4(f0.x, f0.y, f1.x, f1.y);
}

// ---------------------------------------------------------------------------
// Dual roll: grid.y selects (in,out,mode) pair. fp16 tile in smem either way
// (f2h converts during coalesced fill — identical rn rounding point).
// Scatter loop handles channel PAIRS with one half2 store.
// MODE 0: H,+c  1: W,+c  2: W,-c
// ---------------------------------------------------------------------------
template <int M0, int M1, bool INH>
__launch_bounds__(256)
__global__ void roll2_k(const void* inA_, void* outA_,
                        const void* inB_, void* outB_) {
    __shared__ __half tile[56 * 128];
    const int tid = threadIdx.x;
    const int mode = (blockIdx.y == 0) ? M0 : M1;
    const void* in_ = blockIdx.y ? inB_ : inA_;
    __half* out = (__half*)(blockIdx.y ? outB_ : outA_);
    const int b = blockIdx.x / 56;
    const int f = blockIdx.x % 56;
    const size_t base   = (mode == 0) ? ((size_t)b * Nn + f) * 128
                                      : ((size_t)(b * 56 + f) * 56) * 128;
    const int    stride = (mode == 0) ? 56 * 128 : 128;

    if (INH) {
        const __half* in = (const __half*)in_;
        #pragma unroll
        for (int e = tid; e < 56 * 16; e += 256) {
            int rowi = e >> 4, cq = e & 15;
            ((uint4*)tile)[rowi * 16 + cq] =
                *(const uint4*)(in + base + (size_t)rowi * stride + cq * 8);
        }
    } else {
        const float* in = (const float*)in_;
        #pragma unroll
        for (int e = tid; e < 56 * 16; e += 256) {
            int rowi = e >> 4, cq = e & 15;
            const float* p = in + base + (size_t)rowi * stride + cq * 8;
            float4 v0 = *(const float4*)p;
            float4 v1 = *(const float4*)(p + 4);
            uint4 h;
            h.x = pack2(v0.x, v0.y); h.y = pack2(v0.z, v0.w);
            h.z = pack2(v1.x, v1.y); h.w = pack2(v1.z, v1.w);
            ((uint4*)tile)[rowi * 16 + cq] = h;
        }
    }
    __syncthreads();

    #pragma unroll
    for (int e = tid; e < 56 * 64; e += 256) {
        int pos = e >> 6, c = (e & 63) * 2;
        int cm0 = c;     if (cm0 >= 56) cm0 -= 56; if (cm0 >= 56) cm0 -= 56;
        int cm1 = c + 1; if (cm1 >= 56) cm1 -= 56; if (cm1 >= 56) cm1 -= 56;
        int s0, s1;
        if (mode == 2) {
            s0 = pos + cm0; if (s0 >= 56) s0 -= 56;
            s1 = pos + cm1; if (s1 >= 56) s1 -= 56;
        } else {
            s0 = pos - cm0; if (s0 < 0) s0 += 56;
            s1 = pos - cm1; if (s1 < 0) s1 += 56;
        }
        __half2 hv = __halves2half2(tile[s0 * 128 + c], tile[s1 * 128 + c + 1]);
        *(__half2*)(out + base + (size_t)pos * stride + c) = hv;
    }
}

// ---------------------------------------------------------------------------
// FP16 GEMM (m16n8k16, fp32 accum), R14/R16-validated structure.
// ---------------------------------------------------------------------------
enum { EPI_GELU = 0, EPI_BIAS = 1, EPI_RES = 2 };
constexpr int SM_ALL = 64 * 1024 + 16 * 1024;

template <int K, int EPI, int AMODE, bool BT, int MULTI, bool AH, bool OH>
__launch_bounds__(256, 2)
__global__ void gemm_k(const float* __restrict__ A0, const float* __restrict__ A1,
                       const float* __restrict__ B0, const float* __restrict__ B1,
                       const float* __restrict__ B2,
                       const float* __restrict__ bias0, const float* __restrict__ bias1,
                       const float* __restrict__ bias2,
                       const float* __restrict__ res,
                       const float* __restrict__ p0, const float* __restrict__ p1,
                       const float* __restrict__ p2, const float* __restrict__ p3,
                       float* __restrict__ C0, float* __restrict__ C1,
                       float* __restrict__ C2) {
    extern __shared__ char smemc[];
    uint2* Bs  = (uint2*)smemc;
    char*  Asb = smemc + 65536;

    const float* Am = A0;
    const float* Bm = B0;
    const float* bias = bias0;
    float* Cm = C0;
    if (MULTI == 1) {
        int y = blockIdx.y;
        if (y == 1) { Bm = B1; bias = bias1; Cm = C1; }
        else if (y == 2) { Bm = B2; bias = bias2; Cm = C2; }
    } else if (MULTI == 2) {
        if (blockIdx.y == 1) { Am = A1; Bm = B1; bias = bias1; Cm = C1; }
    }

    const int tid  = threadIdx.x;
    const int lane = tid & 31;
    const int wid  = tid >> 5;
    const int wm   = wid & 3;
    const int wn   = wid >> 2;
    const int row0 = blockIdx.x * 128;
    const int lr   = lane >> 2;
    const int lc   = lane & 3;

    auto loadB = [&]() {
        for (int frag = wid; frag < (K / 16) * 16; frag += 8) {
            int kc = frag >> 4, nt = frag & 15;
            int kk = kc * 16 + lc * 2, n = nt * 8 + lr;
            float v0, v1, v2, v3;
            if (BT) {
                const float* p = Bm + (size_t)n * K + kk;
                v0 = p[0]; v1 = p[1]; v2 = p[8]; v3 = p[9];
            } else {
                v0 = Bm[(size_t)kk * 128 + n];
                v1 = Bm[(size_t)(kk + 1) * 128 + n];
                v2 = Bm[(size_t)(kk + 8) * 128 + n];
                v3 = Bm[(size_t)(kk + 9) * 128 + n];
            }
            Bs[frag * 32 + lane] = make_uint2(pack2(v0, v1), pack2(v2, v3));
        }
    };

    const int arow = tid >> 3;
    const int ac4  = tid & 7;
    float mrow[4], rrow[4];
    if (AMODE == 2) {
        #pragma unroll
        for (int i = 0; i < 4; i++) {
            int gr = row0 + arow + i * 32;
            mrow[i] = p0[gr];
            rrow[i] = p1[gr];
        }
    }

    auto fetch4 = [&](int i, int c) -> float4 {
        int gr = row0 + arow + i * 32;
        float4 v;
        if (AMODE == 0) {
            if (AH)
                v = half4_to_f4(*(const uint2*)((const __half*)Am + (size_t)gr * K + c));
            else
                v = *(const float4*)(Am + (size_t)gr * K + c);
        } else {
            if (c < 128) {
                if (AH && AMODE == 3)
                    v = half4_to_f4(*(const uint2*)((const __half*)A0 + (size_t)gr * 128 + c));
                else
                    v = *(const float4*)(A0 + (size_t)gr * 128 + c);
            } else {
                v = *(const float4*)(A1 + (size_t)gr * 128 + (c - 128));
            }
            if (AMODE == 2) {
                float4 g = *(const float4*)(p2 + c);
                float4 bb = *(const float4*)(p3 + c);
                float mn = mrow[i], rs = rrow[i];
                v.x = (v.x - mn) * rs * g.x + bb.x;
                v.y = (v.y - mn) * rs * g.y + bb.y;
                v.z = (v.z - mn) * rs * g.z + bb.z;
                v.w = (v.w - mn) * rs * g.w + bb.w;
            } else if (AMODE == 3) {
                if (c >= 128) {
                    float4 sa = *(const float4*)(p0 + c - 128);
                    float4 ha = *(const float4*)(p1 + c - 128);
                    float4 sb = *(const float4*)(p2 + c - 128);
                    float4 hb = *(const float4*)(p3 + c - 128);
                    v.x = fmaxf(v.x * sa.x + ha.x, 0.f) * sb.x + hb.x;
                    v.y = fmaxf(v.y * sa.y + ha.y, 0.f) * sb.y + hb.y;
                    v.z = fmaxf(v.z * sa.z + ha.z, 0.f) * sb.z + hb.z;
                    v.w = fmaxf(v.w * sa.w + ha.w, 0.f) * sb.w + hb.w;
                }
            }
        }
        return v;
    };

    float4 pa[2][4];
    auto gather = [&](int kc, int set) {
        int c = kc + ac4 * 4;
        #pragma unroll
        for (int i = 0; i < 4; i++) pa[set][i] = fetch4(i, c);
    };

    loadB();
    gather(0, 0);
    gather(32, 1);

    float acc[2][8][4] = {};
    constexpr int NS = K / 32;

    #pragma unroll
    for (int s = 0; s < NS; s++) {
        const int set = s & 1;
        char* Ab = Asb + set * 8192;
        #pragma unroll
        for (int i = 0; i < 4; i++) {
            int row = arow + i * 32;
            uint2 hv = make_uint2(pack2(pa[set][i].x, pa[set][i].y),
                                  pack2(pa[set][i].z, pa[set][i].w));
            *(uint2*)(Ab + row * 64 + 8 * (ac4 ^ (row & 7))) = hv;
        }
        __syncthreads();
        if (s + 2 < NS) gather((s + 2) * 32, set);
        #pragma unroll
        for (int kc = 0; kc < 2; kc++) {
            const int g   = kc * 4 + (lc >> 1);
            const int g2  = g + 2;
            const int off = (lc & 1) * 4;
            uint32_t af[2][4];
            #pragma unroll
            for (int mt2 = 0; mt2 < 2; mt2++) {
                int r = wm * 32 + mt2 * 16 + lr;
                int q = r & 7;
                const char* r1p = Ab + r * 64 + off;
                const char* r2p = Ab + (r + 8) * 64 + off;
                af[mt2][0] = *(const uint32_t*)(r1p + 8 * (g  ^ q));
                af[mt2][1] = *(const uint32_t*)(r2p + 8 * (g  ^ q));
                af[mt2][2] = *(const uint32_t*)(r1p + 8 * (g2 ^ q));
                af[mt2][3] = *(const uint32_t*)(r2p + 8 * (g2 ^ q));
            }
            const int cb = (s * 2 + kc) * 16 + wn * 8;
            #pragma unroll
            for (int u = 0; u < 8; u++) {
                uint2 b = Bs[(cb + u) * 32 + lane];
                mma_f16(acc[0][u], af[0][0], af[0][1], af[0][2], af[0][3], b.x, b.y);
                mma_f16(acc[1][u], af[1][0], af[1][1], af[1][2], af[1][3], b.x, b.y);
            }
        }
    }

    const int ec = lc * 2;
    #pragma unroll
    for (int t = 0; t < 2; t++) {
        int m0 = row0 + wm * 32 + t * 16 + lr;
        #pragma unroll
        for (int u = 0; u < 8; u++) {
            int n = wn * 64 + u * 8 + ec;
            float b0 = bias[n], b1 = bias[n + 1];
            float v0 = acc[t][u][0] + b0;
            float v1 = acc[t][u][1] + b1;
            float v2 = acc[t][u][2] + b0;
            float v3 = acc[t][u][3] + b1;
            if (EPI == EPI_GELU) {
                v0 = 0.5f * v0 * (1.0f + erff(v0 * 0.70710678f));
                v1 = 0.5f * v1 * (1.0f + erff(v1 * 0.70710678f));
                v2 = 0.5f * v2 * (1.0f + erff(v2 * 0.70710678f));
                v3 = 0.5f * v3 * (1.0f + erff(v3 * 0.70710678f));
            } else if (EPI == EPI_RES) {
                float2 r0 = *(const float2*)(res + (size_t)m0 * 128 + n);
                float2 rr = *(const float2*)(res + (size_t)(m0 + 8) * 128 + n);
                v0 += r0.x; v1 += r0.y; v2 += rr.x; v3 += rr.y;
            }
            if (OH) {
                __half* Ch = (__half*)Cm;
                *(uint32_t*)(Ch + (size_t)m0 * 128 + n)       = pack2(v0, v1);
                *(uint32_t*)(Ch + (size_t)(m0 + 8) * 128 + n) = pack2(v2, v3);
            } else {
                *(float2*)(Cm + (size_t)m0 * 128 + n)       = make_float2(v0, v1);
                *(float2*)(Cm + (size_t)(m0 + 8) * 128 + n) = make_float2(v2, v3);
            }
        }
    }
}

// ---------------------------------------------------------------------------
// LayerNorm stats only
// ---------------------------------------------------------------------------
__global__ void ln_stats_k(const float* __restrict__ x1a, const float* __restrict__ x2a,
                           float* __restrict__ mean, float* __restrict__ rstd) {
    int warp = (blockIdx.x * blockDim.x + threadIdx.x) >> 5;
    int lane = threadIdx.x & 31;
    if (warp >= Mm) return;
    float s = 0.f, sq = 0.f;
    #pragma unroll
    for (int kq = 0; kq < 4; kq++) {
        float a = x1a[(size_t)warp * 128 + lane + 32 * kq];
        float b = x2a[(size_t)warp * 128 + lane + 32 * kq];
        s += a + b; sq += a * a + b * b;
    }
    #pragma unroll
    for (int o = 16; o > 0; o >>= 1) {
        s  += __shfl_xor_sync(0xffffffffu, s, o);
        sq += __shfl_xor_sync(0xffffffffu, sq, o);
    }
    if (lane == 0) {
        float mu = s * (1.f / 256.f);
        float var = sq * (1.f / 256.f) - mu * mu;
        mean[warp] = mu;
        rstd[warp] = rsqrtf(var + 1e-5f);
    }
}

// ---------------------------------------------------------------------------
// Window attention (fp16, R15/R16 layout) + fused BN1 partial stats.
// ---------------------------------------------------------------------------
constexpr int QH = 136;
constexpr int PH = 72;
constexpr int VH = 136;
constexpr int ATTN_HALFS = 2 * 64 * QH + 64 * VH;           // 26112 halfs
constexpr int ATTN_SMEM  = ATTN_HALFS * 2 + 2 * 512 * 4;    // + sm_s/sm_q

__launch_bounds__(256)
__global__ void attn_k(const __half* __restrict__ q, const __half* __restrict__ k,
                       const __half* __restrict__ v, float* __restrict__ out,
                       float* __restrict__ part) {
    extern __shared__ __half smh[];
    __half* Qs = smh;
    __half* Ks = Qs + 64 * QH;
    __half* Vs = Ks + 64 * QH;
    __half* Ps = Qs;
    float* sm_s = (float*)(smh + ATTN_HALFS);
    float* sm_q = sm_s + 512;

    const int widx = blockIdx.x;
    const int b = widx >> 6, wh = (widx >> 3) & 7, ww = widx & 7;
    const int tid  = threadIdx.x;
    const int lane = tid & 31, w = tid >> 5;
    const int wm = w & 3, wn = w >> 2;
    const int lr = lane >> 2, lc = lane & 3;

    auto grow = [&](int i) -> size_t {
        return ((size_t)(b * Nn + (wh * 7 + i / 7) * 56 + ww * 7 + (i % 7))) * 128;
    };

    for (int e = tid; e < 49 * 32; e += 256) {
        int i = e >> 5, c4 = (e & 31) * 4;
        size_t g = grow(i) + c4;
        *(uint2*)(Qs + i * QH + c4) = *(const uint2*)(q + g);
        *(uint2*)(Ks + i * QH + c4) = *(const uint2*)(k + g);
        *(uint2*)(Vs + i * VH + c4) = *(const uint2*)(v + g);
    }
    for (int e = tid; e < 15 * VH / 2; e += 256)
        ((uint32_t*)(Vs + 49 * VH))[e] = 0u;
    __syncthreads();

    float acc[4][4] = {};
    #pragma unroll
    for (int ks = 0; ks < 8; ks++) {
        int r = wm * 16 + lr, c = ks * 16 + lc * 2;
        uint32_t a0 = *(const uint32_t*)(Qs + r * QH + c);
        uint32_t a1 = *(const uint32_t*)(Qs + (r + 8) * QH + c);
        uint32_t a2 = *(const uint32_t*)(Qs + r * QH + c + 8);
        uint32_t a3 = *(const uint32_t*)(Qs + (r + 8) * QH + c + 8);
        #pragma unroll
        for (int u = 0; u < 4; u++) {
            int n = wn * 32 + u * 8 + lr;
            uint32_t b0 = *(const uint32_t*)(Ks + n * QH + c);
            uint32_t b1 = *(const uint32_t*)(Ks + n * QH + c + 8);
            mma_f16(acc[u], a0, a1, a2, a3, b0, b1);
        }
    }
    __syncthreads();
    #pragma unroll
    for (int u = 0; u < 4; u++) {
        int r = wm * 16 + lr, n = wn * 32 + u * 8 + lc * 2;
        *(uint32_t*)(Ps + r * PH + n)       = pack2(acc[u][0], acc[u][1]);
        *(uint32_t*)(Ps + (r + 8) * PH + n) = pack2(acc[u][2], acc[u][3]);
    }
    __syncthreads();

    if (tid < 49) {
        const float scale = 0.08838834764831845f;
        __half* r = Ps + tid * PH;
        float mx = __half2float(r[0]);
        #pragma unroll 7
        for (int j = 1; j < 49; j++) mx = fmaxf(mx, __half2float(r[j]));
        float s = 0.f;
        #pragma unroll 7
        for (int j = 0; j < 49; j++) {
            float e = expf((__half2float(r[j]) - mx) * scale);
            r[j] = __float2half(e);
            s += e;
        }
        float inv = 1.f / s;
        #pragma unroll 7
        for (int j = 0; j < 49; j++)
            r[j] = __float2half(__half2float(r[j]) * inv);
        #pragma unroll
        for (int j = 49; j < 64; j++) r[j] = __float2half(0.f);
    }
    __syncthreads();

    float o[8][4] = {};
    #pragma unroll
    for (int k8 = 0; k8 < 8; k8++) {
        int r = wm * 16 + lr, c = k8 * 8 + lc;
        float4 a = make_float4(__half2float(Ps[r * PH + c]),
                               __half2float(Ps[(r + 8) * PH + c]),
                               __half2float(Ps[r * PH + c + 4]),
                               __half2float(Ps[(r + 8) * PH + c + 4]));
        #pragma unroll
        for (int u = 0; u < 8; u++) {
            int n = wn * 64 + u * 8 + lr;
            float2 bf = make_float2(__half2float(Vs[c * VH + n]),
                                    __half2float(Vs[(c + 4) * VH + n]));
            mma_tf32(o[u], a, bf);
        }
    }
    int r0 = wm * 16 + lr;
    #pragma unroll
    for (int u = 0; u < 8; u++) {
        int n = wn * 64 + u * 8 + lc * 2;
        if (r0 < 49)     *(float2*)(out + grow(r0) + n)     = make_float2(o[u][0], o[u][1]);
        if (r0 + 8 < 49) *(float2*)(out + grow(r0 + 8) + n) = make_float2(o[u][2], o[u][3]);
    }

    // ---- fused BN1 partial stats over this window's 49 valid rows ----
    #pragma unroll
    for (int u = 0; u < 8; u++) {
        float a0 = (r0 < 49)     ? o[u][0] : 0.f;
        float a1 = (r0 < 49)     ? o[u][1] : 0.f;
        float a2 = (r0 + 8 < 49) ? o[u][2] : 0.f;
        float a3 = (r0 + 8 < 49) ? o[u][3] : 0.f;
        float s0 = a0 + a2, q0 = a0 * a0 + a2 * a2;
        float s1 = a1 + a3, q1 = a1 * a1 + a3 * a3;
        #pragma unroll
        for (int off = 16; off >= 4; off >>= 1) {
            s0 += __shfl_down_sync(0xffffffffu, s0, off);
            q0 += __shfl_down_sync(0xffffffffu, q0, off);
            s1 += __shfl_down_sync(0xffffffffu, s1, off);
            q1 += __shfl_down_sync(0xffffffffu, q1, off);
        }
        if (lr == 0) {
            int ch = wn * 64 + u * 8 + lc * 2;
            sm_s[wm * 128 + ch]     = s0;
            sm_s[wm * 128 + ch + 1] = s1;
            sm_q[wm * 128 + ch]     = q0;
            sm_q[wm * 128 + ch + 1] = q1;
        }
    }
    __syncthreads();
    if (tid < 128)
        part[(size_t)widx * 256 + tid] =
            sm_s[tid] + sm_s[128 + tid] + sm_s[256 + tid] + sm_s[384 + tid];
    else
        part[(size_t)widx * 256 + tid] =
            sm_q[tid - 128] + sm_q[tid] + sm_q[tid + 128] + sm_q[tid + 256];
}

// ---------------------------------------------------------------------------
// BatchNorm pieces
// ---------------------------------------------------------------------------
__global__ void bn2_stats_k(const float* __restrict__ x,
                            const float* __restrict__ s1, const float* __restrict__ h1,
                            float* __restrict__ part) {
    int c = threadIdx.x & 127;
    int half = threadIdx.x >> 7;
    float sc = s1[c], sh_ = h1[c];
    float s = 0.f, sq = 0.f;
    int rbeg = blockIdx.x * 128 + half;
    int rend = blockIdx.x * 128 + 128;
    for (int r = rbeg; r < rend; r += 2) {
        float vv = fmaxf(x[(size_t)r * 128 + c] * sc + sh_, 0.f);
        s += vv; sq += vv * vv;
    }
    __shared__ float shm[512];
    shm[threadIdx.x] = s;
    shm[256 + threadIdx.x] = sq;
    __syncthreads();
    if (half == 0) {
        part[blockIdx.x * 256 + c]       = shm[c] + shm[128 + c];
        part[blockIdx.x * 256 + 128 + c] = shm[256 + c] + shm[256 + 128 + c];
    }
}

__global__ void bn_reduce_k(const float* __restrict__ part, const float* __restrict__ g,
                            const float* __restrict__ beta, float* __restrict__ scale,
                            float* __restrict__ shift, int nb) {
    int c = threadIdx.x;
    float s = 0.f, sq = 0.f;
    for (int i = 0; i < nb; i++) {
        s  += part[i * 256 + c];
        sq += part[i * 256 + 128 + c];
    }
    float mean = s / (float)Mm;
    float var  = sq / (float)Mm - mean * mean;
    float sc_  = g[c] * rsqrtf(var + 1e-5f);
    scale[c] = sc_;
    shift[c] = beta[c] - mean * sc_;
}

// ---------------------------------------------------------------------------
// Host launch
// ---------------------------------------------------------------------------
static float* symaddr(const void* devsym) {
    void* p = nullptr;
    cudaGetSymbolAddress(&p, devsym);
    return (float*)p;
}

extern "C" void kernel_launch(void* const* d_in, const int* in_sizes, int n_in,
                              void* d_out, int out_size) {
    const float* x     = (const float*)d_in[0];
    const float* fc1_w = (const float*)d_in[1];
    const float* fc1_b = (const float*)d_in[2];
    const float* fc2_w = (const float*)d_in[3];
    const float* fc2_b = (const float*)d_in[4];
    const float* fc3_w = (const float*)d_in[5];
    const float* fc3_b = (const float*)d_in[6];
    const float* fc4_w = (const float*)d_in[7];
    const float* fc4_b = (const float*)d_in[8];
    const float* fc5_w = (const float*)d_in[9];
    const float* fc5_b = (const float*)d_in[10];
    const float* fc6_w = (const float*)d_in[11];
    const float* fc6_b = (const float*)d_in[12];
    const float* ln_w  = (const float*)d_in[13];
    const float* ln_b  = (const float*)d_in[14];
    const float* q_w   = (const float*)d_in[15];
    const float* q_b   = (const float*)d_in[16];
    const float* k_w   = (const float*)d_in[17];
    const float* k_b   = (const float*)d_in[18];
    const float* v_w   = (const float*)d_in[19];
    const float* v_b   = (const float*)d_in[20];
    const float* bn1_g = (const float*)d_in[21];
    const float* bn1_b = (const float*)d_in[22];
    const float* bn2_g = (const float*)d_in[23];
    const float* bn2_b = (const float*)d_in[24];

    float* t0   = symaddr(g_t0);
    float* t1   = symaddr(g_t1);
    float* x1a  = symaddr(g_x1a);
    float* x2a  = symaddr(g_x2a);
    float* qb   = symaddr(g_q);
    float* kb   = symaddr(g_k);
    float* vb   = symaddr(g_v);
    float* att  = symaddr(g_att);
    float* stat = symaddr(g_stats);
    float* mean = stat;
    float* rstd = stat + Mm;
    float* part = symaddr(g_part);
    float* s1   = symaddr(g_s1);
    float* h1   = symaddr(g_h1);
    float* s2   = symaddr(g_s2);
    float* h2   = symaddr(g_h2);

    __half* t0h = (__half*)t0;
    __half* t1h = (__half*)t1;
    __half* qbh = (__half*)qb;
    __half* kbh = (__half*)kb;
    __half* vbh = (__half*)vb;

    const int gridR = Bb * 56;
    const int gridG = Mm / 128;          // 784

    auto setsm = [](const void* f) {
        cudaFuncSetAttribute(f, cudaFuncAttributeMaxDynamicSharedMemorySize, SM_ALL);
    };
    setsm((const void*)gemm_k<128, EPI_GELU, 0, false, 2, true,  true >);
    setsm((const void*)gemm_k<128, EPI_RES,  0, false, 2, true,  false>);
    setsm((const void*)gemm_k<128, EPI_BIAS, 0, true,  1, false, true >);
    setsm((const void*)gemm_k<256, EPI_RES,  2, false, 0, false, true >);
    setsm((const void*)gemm_k<256, EPI_BIAS, 3, false, 0, true,  false>);
    cudaFuncSetAttribute(attn_k, cudaFuncAttributeMaxDynamicSharedMemorySize, ATTN_SMEM);

    // Dual first rolls of x (fp32 -> fp16): t0h = H,+c ; qbh = W,-c
    roll2_k<0, 2, false><<<dim3(gridR, 2), 256>>>(x, t0h, x, qbh);

    // fc1 || fc3 (DUAL, half A, half out): -> t1h, kbh
    gemm_k<128, EPI_GELU, 0, false, 2, true, true><<<dim3(gridG, 2), 256, SM_ALL>>>(
        (const float*)t0h, (const float*)qbh, fc1_w, fc3_w, nullptr,
        fc1_b, fc3_b, nullptr, nullptr,
        nullptr, nullptr, nullptr, nullptr, (float*)t1h, (float*)kbh, nullptr);

    // Dual mid rolls (fp16 -> fp16): t1h -(W,+c)-> t0h ; kbh -(H,+c)-> qbh
    roll2_k<1, 0, true><<<dim3(gridR, 2), 256>>>(t1h, t0h, kbh, qbh);

    // fc2 || fc4 (DUAL, half A, fp32 out) + residual x -> x1a, x2a
    gemm_k<128, EPI_RES, 0, false, 2, true, false><<<dim3(gridG, 2), 256, SM_ALL>>>(
        (const float*)t0h, (const float*)qbh, fc2_w, fc4_w, nullptr,
        fc2_b, fc4_b, nullptr, x,
        nullptr, nullptr, nullptr, nullptr, x1a, x2a, nullptr);

    // LN stats + fc5 (LN folded, fp32 A, half out) + residual -> t0h
    ln_stats_k<<<Mm / 8, 256>>>(x1a, x2a, mean, rstd);
    gemm_k<256, EPI_RES, 2, false, 0, false, true><<<gridG, 256, SM_ALL>>>(
        x1a, x2a, fc5_w, nullptr, nullptr, fc5_b, nullptr, nullptr, x,
        mean, rstd, ln_w, ln_b, (float*)t0h, nullptr, nullptr);

    // q/k/v (fp32 A = x, half outs)
    gemm_k<128, EPI_BIAS, 0, true, 1, false, true><<<dim3(gridG, 3), 256, SM_ALL>>>(
        x, nullptr, q_w, k_w, v_w, q_b, k_b, v_b, nullptr,
        nullptr, nullptr, nullptr, nullptr, (float*)qbh, (float*)kbh, (float*)vbh);

    // Window attention (fp16) with fused BN1 partial stats
    attn_k<<<2048, 256, ATTN_SMEM>>>(qbh, kbh, vbh, att, part);

    // BN1 reduce (2048 partials) -> BN2 stats (read-only) -> BN2 reduce
    bn_reduce_k<<<1, 128>>>(part, bn1_g, bn1_b, s1, h1, 2048);
    bn2_stats_k<<<784, 256>>>(att, s1, h1, part);
    bn_reduce_k<<<1, 128>>>(part, bn2_g, bn2_b, s2, h2, 784);

    // Final: out = [x1(half) | relu(bn1(att))*bn2] @ fc6 + b
    gemm_k<256, EPI_BIAS, 3, false, 0, true, false><<<gridG, 256, SM_ALL>>>(
        (const float*)t0h, att, fc6_w, nullptr, nullptr, fc6_b, nullptr, nullptr, nullptr,
        s1, h1, s2, h2, (float*)d_out, nullptr, nullptr);
}